// round 6
// baseline (speedup 1.0000x reference)
#include <cuda_runtime.h>
#include <math.h>

#define Bv    8
#define Sv    4096
#define Tv    512
#define HIDv  512
#define HEADSv 8
#define DKv   64

// Scratch (allocation-free: __device__ globals)
__device__ float g_Q[Bv * Tv * HIDv];        // 8 MB
__device__ float g_K[Bv * Sv * HIDv];        // 64 MB
__device__ float g_V[Bv * Sv * HIDv];        // 64 MB
__device__ float g_ctx[Bv * Tv * HIDv];      // 8 MB

// ---------------------------------------------------------------------------
// C[M,512] = A[M,512] @ W[512,512]^T + bias   (row-major, K contiguous)
// 128x128 tile, BK=16, 256 threads, 8x8 microtile per thread.
// Smem held k-major (As[k][m]) so the inner loop does 4x LDS.128 per k-step:
// 0.25 LDS-floats per FMA -> FMA-issue-bound, not smem-crossbar-bound.
// ---------------------------------------------------------------------------
__global__ __launch_bounds__(256) void gemm_bias_kernel(
    const float* __restrict__ A, const float* __restrict__ W,
    const float* __restrict__ bias, float* __restrict__ C, int M)
{
    const int BM = 128, BK = 16, LDS_PAD = 132;   // 128+4 keeps 16B alignment
    __shared__ float As[BK * LDS_PAD];
    __shared__ float Ws[BK * LDS_PAD];

    const int tid = threadIdx.x;
    const int tx = tid & 15, ty = tid >> 4;
    const int m0 = blockIdx.y * BM;
    const int n0 = blockIdx.x * BM;

    float acc[8][8] = {};

    for (int k0 = 0; k0 < 512; k0 += BK) {
        // Load 128x16 tiles of A and W, transposed into smem (k-major).
        #pragma unroll
        for (int r = 0; r < 2; r++) {
            int f   = tid + r * 256;        // 0..511 float4 slots
            int row = f >> 2;               // 0..127
            int kq  = (f & 3) * 4;          // 0,4,8,12
            float4 a = *(const float4*)&A[(size_t)(m0 + row) * 512 + k0 + kq];
            As[(kq + 0) * LDS_PAD + row] = a.x;
            As[(kq + 1) * LDS_PAD + row] = a.y;
            As[(kq + 2) * LDS_PAD + row] = a.z;
            As[(kq + 3) * LDS_PAD + row] = a.w;
            float4 w = *(const float4*)&W[(size_t)(n0 + row) * 512 + k0 + kq];
            Ws[(kq + 0) * LDS_PAD + row] = w.x;
            Ws[(kq + 1) * LDS_PAD + row] = w.y;
            Ws[(kq + 2) * LDS_PAD + row] = w.z;
            Ws[(kq + 3) * LDS_PAD + row] = w.w;
        }
        __syncthreads();

        #pragma unroll
        for (int kk = 0; kk < BK; kk++) {
            float a[8], b[8];
            *(float4*)&a[0] = *(const float4*)&As[kk * LDS_PAD + ty * 8];
            *(float4*)&a[4] = *(const float4*)&As[kk * LDS_PAD + ty * 8 + 4];
            *(float4*)&b[0] = *(const float4*)&Ws[kk * LDS_PAD + tx * 8];
            *(float4*)&b[4] = *(const float4*)&Ws[kk * LDS_PAD + tx * 8 + 4];
            #pragma unroll
            for (int i = 0; i < 8; i++)
                #pragma unroll
                for (int j = 0; j < 8; j++)
                    acc[i][j] += a[i] * b[j];
        }
        __syncthreads();
    }

    // Epilogue: add bias, vectorized stores.
    float bb[8];
    *(float4*)&bb[0] = *(const float4*)&bias[n0 + tx * 8];
    *(float4*)&bb[4] = *(const float4*)&bias[n0 + tx * 8 + 4];
    #pragma unroll
    for (int i = 0; i < 8; i++) {
        float4 o0, o1;
        o0.x = acc[i][0] + bb[0]; o0.y = acc[i][1] + bb[1];
        o0.z = acc[i][2] + bb[2]; o0.w = acc[i][3] + bb[3];
        o1.x = acc[i][4] + bb[4]; o1.y = acc[i][5] + bb[5];
        o1.z = acc[i][6] + bb[6]; o1.w = acc[i][7] + bb[7];
        size_t base = (size_t)(m0 + ty * 8 + i) * 512 + n0 + tx * 8;
        *(float4*)&C[base]     = o0;
        *(float4*)&C[base + 4] = o1;
    }
}

// ---------------------------------------------------------------------------
// Flash attention: one block per (64-query tile, head, batch).
// Row softmax state (m, l) lives in registers, replicated across the 16
// threads (one half-warp) that own each row; reductions via shfl(width=16).
// 3 barriers per S-chunk. mask is int32 on the wire (bool widened).
// ---------------------------------------------------------------------------
__global__ __launch_bounds__(256) void attn_kernel(const int* __restrict__ mask)
{
    extern __shared__ float sm[];
    float* Qs   = sm;                    // 64*65
    float* Ks   = Qs + 64 * 65;          // 64*65
    float* Vs   = Ks + 64 * 65;          // 64*65
    float* Ps   = Vs + 64 * 65;          // 64*65
    float* mneg = Ps + 64 * 65;          // 64

    const int tx = threadIdx.x, ty = threadIdx.y;
    const int tid = ty * 16 + tx;
    const int t0 = blockIdx.x * 64;
    const int h  = blockIdx.y;
    const int b  = blockIdx.z;

    // load Q tile (64 x 64)
    #pragma unroll
    for (int r = 0; r < 4; r++) {
        int idx = tid + r * 256;
        int row = idx >> 4;
        int c4  = (idx & 15) * 4;
        float4 q = *(const float4*)&g_Q[((size_t)(b * Tv + t0 + row)) * HIDv + h * DKv + c4];
        Qs[row * 65 + c4 + 0] = q.x; Qs[row * 65 + c4 + 1] = q.y;
        Qs[row * 65 + c4 + 2] = q.z; Qs[row * 65 + c4 + 3] = q.w;
    }

    float rowMr[4], rowLr[4];
    #pragma unroll
    for (int i = 0; i < 4; i++) { rowMr[i] = -1e30f; rowLr[i] = 0.0f; }

    float acc[4][4] = {};
    __syncthreads();

    for (int s0 = 0; s0 < Sv; s0 += 64) {
        // load K,V tiles (+ mask strip)
        #pragma unroll
        for (int r = 0; r < 4; r++) {
            int idx = tid + r * 256;
            int row = idx >> 4;
            int c4  = (idx & 15) * 4;
            size_t g = ((size_t)(b * Sv + s0 + row)) * HIDv + h * DKv + c4;
            float4 k = *(const float4*)&g_K[g];
            Ks[row * 65 + c4 + 0] = k.x; Ks[row * 65 + c4 + 1] = k.y;
            Ks[row * 65 + c4 + 2] = k.z; Ks[row * 65 + c4 + 3] = k.w;
            float4 v = *(const float4*)&g_V[g];
            Vs[row * 65 + c4 + 0] = v.x; Vs[row * 65 + c4 + 1] = v.y;
            Vs[row * 65 + c4 + 2] = v.z; Vs[row * 65 + c4 + 3] = v.w;
        }
        if (tid < 64) mneg[tid] = (mask[b * Sv + s0 + tid] != 0) ? 0.0f : -1e20f;
        __syncthreads();

        // raw scores 4x4 (scaled + mask)
        float sc[4][4] = {};
        #pragma unroll 4
        for (int kk = 0; kk < 64; kk++) {
            float a[4], bb[4];
            #pragma unroll
            for (int i = 0; i < 4; i++) a[i]  = Qs[(ty * 4 + i) * 65 + kk];
            #pragma unroll
            for (int j = 0; j < 4; j++) bb[j] = Ks[(tx * 4 + j) * 65 + kk];
            #pragma unroll
            for (int i = 0; i < 4; i++)
                #pragma unroll
                for (int j = 0; j < 4; j++)
                    sc[i][j] += a[i] * bb[j];
        }
        float mcol[4];
        #pragma unroll
        for (int j = 0; j < 4; j++) mcol[j] = mneg[tx * 4 + j];
        #pragma unroll
        for (int i = 0; i < 4; i++)
            #pragma unroll
            for (int j = 0; j < 4; j++)
                sc[i][j] = sc[i][j] * 0.125f + mcol[j];

        // Online softmax, fully in registers.
        // Row ty*4+i is owned by the 16 lanes (ty*16 + tx), a half-warp:
        // reduce with shfl_xor over width 16; state replicated per-lane.
        #pragma unroll
        for (int i = 0; i < 4; i++) {
            float mx = fmaxf(fmaxf(sc[i][0], sc[i][1]), fmaxf(sc[i][2], sc[i][3]));
            #pragma unroll
            for (int o = 8; o >= 1; o >>= 1)
                mx = fmaxf(mx, __shfl_xor_sync(0xffffffffu, mx, o, 16));

            float mn = fmaxf(rowMr[i], mx);
            float f  = __expf(rowMr[i] - mn);
            rowMr[i] = mn;

            float p0 = __expf(sc[i][0] - mn);
            float p1 = __expf(sc[i][1] - mn);
            float p2 = __expf(sc[i][2] - mn);
            float p3 = __expf(sc[i][3] - mn);
            float se = (p0 + p1) + (p2 + p3);
            #pragma unroll
            for (int o = 8; o >= 1; o >>= 1)
                se += __shfl_xor_sync(0xffffffffu, se, o, 16);
            rowLr[i] = rowLr[i] * f + se;

            #pragma unroll
            for (int j = 0; j < 4; j++) acc[i][j] *= f;

            float* pr = &Ps[(ty * 4 + i) * 65 + tx * 4];
            pr[0] = p0; pr[1] = p1; pr[2] = p2; pr[3] = p3;
        }
        __syncthreads();

        // acc += P @ V
        #pragma unroll 4
        for (int s = 0; s < 64; s++) {
            float p[4], v[4];
            #pragma unroll
            for (int i = 0; i < 4; i++) p[i] = Ps[(ty * 4 + i) * 65 + s];
            #pragma unroll
            for (int j = 0; j < 4; j++) v[j] = Vs[s * 65 + tx * 4 + j];
            #pragma unroll
            for (int i = 0; i < 4; i++)
                #pragma unroll
                for (int j = 0; j < 4; j++)
                    acc[i][j] += p[i] * v[j];
        }
        __syncthreads();
    }

    // normalize + write ctx
    #pragma unroll
    for (int i = 0; i < 4; i++) {
        float inv = 1.0f / rowLr[i];
        #pragma unroll
        for (int j = 0; j < 4; j++)
            g_ctx[((size_t)(b * Tv + t0 + ty * 4 + i)) * HIDv + h * DKv + tx * 4 + j] =
                acc[i][j] * inv;
    }
}

// ---------------------------------------------------------------------------

extern "C" void kernel_launch(void* const* d_in, const int* in_sizes, int n_in,
                              void* d_out, int out_size)
{
    const float* inputs  = (const float*)d_in[0];
    const float* targets = (const float*)d_in[1];
    const int*   mask    = (const int*)d_in[2];     // bool widened to int32
    const float* Wq = (const float*)d_in[3];
    const float* bq = (const float*)d_in[4];
    const float* Wk = (const float*)d_in[5];
    const float* bk = (const float*)d_in[6];
    const float* Wv = (const float*)d_in[7];
    const float* bv = (const float*)d_in[8];
    const float* Wo = (const float*)d_in[9];
    const float* bo = (const float*)d_in[10];
    float* out = (float*)d_out;

    float *pQ, *pK, *pV, *pC;
    cudaGetSymbolAddress((void**)&pQ, g_Q);
    cudaGetSymbolAddress((void**)&pK, g_K);
    cudaGetSymbolAddress((void**)&pV, g_V);
    cudaGetSymbolAddress((void**)&pC, g_ctx);

    const int ATTN_SMEM = (4 * 64 * 65 + 64) * (int)sizeof(float);
    cudaFuncSetAttribute(attn_kernel, cudaFuncAttributeMaxDynamicSharedMemorySize, ATTN_SMEM);

    dim3 blk256(256);
    dim3 blkAttn(16, 16);

    // Q = targets @ Wq^T + bq    (M = B*T = 4096)
    gemm_bias_kernel<<<dim3(4, 32), blk256>>>(targets, Wq, bq, pQ, Bv * Tv);
    // K = inputs @ Wk^T + bk     (M = B*S = 32768)
    gemm_bias_kernel<<<dim3(4, 256), blk256>>>(inputs, Wk, bk, pK, Bv * Sv);
    // V = inputs @ Wv^T + bv
    gemm_bias_kernel<<<dim3(4, 256), blk256>>>(inputs, Wv, bv, pV, Bv * Sv);
    // attention -> g_ctx
    attn_kernel<<<dim3(Tv / 64, HEADSv, Bv), blkAttn, ATTN_SMEM>>>(mask);
    // out = ctx @ Wo^T + bo
    gemm_bias_kernel<<<dim3(4, 32), blk256>>>(pC, Wo, bo, out, Bv * Tv);
}

// round 7
// speedup vs baseline: 1.1848x; 1.1848x over previous
#include <cuda_runtime.h>
#include <math.h>

#define Bv    8
#define Sv    4096
#define Tv    512
#define HIDv  512
#define HEADSv 8
#define DKv   64

typedef unsigned long long u64;

// Scratch (allocation-free: __device__ globals)
__device__ float g_Q[Bv * Tv * HIDv];        // 8 MB
__device__ float g_K[Bv * Sv * HIDv];        // 64 MB
__device__ float g_V[Bv * Sv * HIDv];        // 64 MB
__device__ float g_ctx[Bv * Tv * HIDv];      // 8 MB

// ---------------- packed f32x2 helpers (FFMA2 path) ----------------
__device__ __forceinline__ u64 pack2(float x, float y) {
    u64 d; asm("mov.b64 %0, {%1, %2};" : "=l"(d) : "f"(x), "f"(y)); return d;
}
__device__ __forceinline__ u64 pdup(float x) { return pack2(x, x); }
__device__ __forceinline__ void unpack2(u64 v, float& x, float& y) {
    asm("mov.b64 {%0, %1}, %2;" : "=f"(x), "=f"(y) : "l"(v));
}
__device__ __forceinline__ u64 fma2(u64 a, u64 b, u64 c) {
    u64 d; asm("fma.rn.f32x2 %0, %1, %2, %3;" : "=l"(d) : "l"(a), "l"(b), "l"(c)); return d;
}
__device__ __forceinline__ u64 mul2(u64 a, u64 b) {
    u64 d; asm("mul.rn.f32x2 %0, %1, %2;" : "=l"(d) : "l"(a), "l"(b)); return d;
}

// FMA-pipe exp (avoids MUFU throughput wall). Valid for x <= 0; exact at 0.
__device__ __forceinline__ float fast_exp(float x) {
    float y = fmaxf(x * 1.4426950408889634f, -126.0f);
    float n = rintf(y);
    float r = y - n;
    float q = 1.5403530394e-4f;
    q = fmaf(q, r, 1.3333558146e-3f);
    q = fmaf(q, r, 9.6181291076e-3f);
    q = fmaf(q, r, 5.5504108664e-2f);
    q = fmaf(q, r, 2.4022650696e-1f);
    q = fmaf(q, r, 6.9314718056e-1f);
    q = fmaf(q, r, 1.0f);
    return q * __int_as_float(((int)n + 127) << 23);
}

// ---------------------------------------------------------------------------
// C[M,512] = A[M,512] @ W[512,512]^T + bias   (row-major, K contiguous)
// 128x128 tile, BK=16, 256 threads, 8x8 microtile, packed f32x2 FMAs.
// ---------------------------------------------------------------------------
__global__ __launch_bounds__(256) void gemm_bias_kernel(
    const float* __restrict__ A, const float* __restrict__ W,
    const float* __restrict__ bias, float* __restrict__ C, int M)
{
    const int BK = 16, LDSP = 132;                // 128+4, keeps 16B alignment
    __shared__ float As[BK * LDSP];
    __shared__ float Ws[BK * LDSP];

    const int tid = threadIdx.x;
    const int tx = tid & 15, ty = tid >> 4;
    const int m0 = blockIdx.y * 128;
    const int n0 = blockIdx.x * 128;

    u64 acc2[8][4];
    #pragma unroll
    for (int i = 0; i < 8; i++)
        #pragma unroll
        for (int j = 0; j < 4; j++) acc2[i][j] = 0ull;

    for (int k0 = 0; k0 < 512; k0 += BK) {
        #pragma unroll
        for (int r = 0; r < 2; r++) {
            int f   = tid + r * 256;
            int row = f >> 2;
            int kq  = (f & 3) * 4;
            float4 a = *(const float4*)&A[(size_t)(m0 + row) * 512 + k0 + kq];
            As[(kq + 0) * LDSP + row] = a.x;
            As[(kq + 1) * LDSP + row] = a.y;
            As[(kq + 2) * LDSP + row] = a.z;
            As[(kq + 3) * LDSP + row] = a.w;
            float4 w = *(const float4*)&W[(size_t)(n0 + row) * 512 + k0 + kq];
            Ws[(kq + 0) * LDSP + row] = w.x;
            Ws[(kq + 1) * LDSP + row] = w.y;
            Ws[(kq + 2) * LDSP + row] = w.z;
            Ws[(kq + 3) * LDSP + row] = w.w;
        }
        __syncthreads();

        #pragma unroll
        for (int kk = 0; kk < BK; kk++) {
            float4 a0 = *(const float4*)&As[kk * LDSP + ty * 8];
            float4 a1 = *(const float4*)&As[kk * LDSP + ty * 8 + 4];
            ulonglong2 w0 = *(const ulonglong2*)&Ws[kk * LDSP + tx * 8];
            ulonglong2 w1 = *(const ulonglong2*)&Ws[kk * LDSP + tx * 8 + 4];
            u64 ww[4] = {w0.x, w0.y, w1.x, w1.y};
            u64 a2[8];
            a2[0] = pdup(a0.x); a2[1] = pdup(a0.y);
            a2[2] = pdup(a0.z); a2[3] = pdup(a0.w);
            a2[4] = pdup(a1.x); a2[5] = pdup(a1.y);
            a2[6] = pdup(a1.z); a2[7] = pdup(a1.w);
            #pragma unroll
            for (int i = 0; i < 8; i++)
                #pragma unroll
                for (int j = 0; j < 4; j++)
                    acc2[i][j] = fma2(a2[i], ww[j], acc2[i][j]);
        }
        __syncthreads();
    }

    float bb[8];
    *(float4*)&bb[0] = *(const float4*)&bias[n0 + tx * 8];
    *(float4*)&bb[4] = *(const float4*)&bias[n0 + tx * 8 + 4];
    #pragma unroll
    for (int i = 0; i < 8; i++) {
        float o[8];
        unpack2(acc2[i][0], o[0], o[1]);
        unpack2(acc2[i][1], o[2], o[3]);
        unpack2(acc2[i][2], o[4], o[5]);
        unpack2(acc2[i][3], o[6], o[7]);
        float4 s0, s1;
        s0.x = o[0] + bb[0]; s0.y = o[1] + bb[1];
        s0.z = o[2] + bb[2]; s0.w = o[3] + bb[3];
        s1.x = o[4] + bb[4]; s1.y = o[5] + bb[5];
        s1.z = o[6] + bb[6]; s1.w = o[7] + bb[7];
        size_t base = (size_t)(m0 + ty * 8 + i) * 512 + n0 + tx * 8;
        *(float4*)&C[base]     = s0;
        *(float4*)&C[base + 4] = s1;
    }
}

// ---------------------------------------------------------------------------
// Flash attention: one block per (256-query tile, head, batch) = 128 blocks.
// 8x8 microtile (tx: 8 key/d groups, ty: 32 query groups), packed f32x2 FMAs,
// FMA-pipe exp, P stored transposed with XOR swizzle for conflict-free loads.
// ---------------------------------------------------------------------------
__global__ __launch_bounds__(256) void attn_kernel(const int* __restrict__ mask)
{
    extern __shared__ float sm[];
    float* Qs   = sm;                    // [64][260]  Q k-major
    float* Ks   = Qs + 64 * 260;         // [64][68]   K k-major
    float* Vs   = Ks + 64 * 68;          // [64][68]   V s-major
    float* Ps   = Vs + 64 * 68;          // [64][260]  P s-major (swizzled cols)
    float* mneg = Ps + 64 * 260;         // [64]

    const int tid = threadIdx.x;
    const int tx = tid & 7;              // key/d group
    const int ty = tid >> 3;             // query group (0..31)
    const int t0 = blockIdx.x * 256;
    const int h  = blockIdx.y;
    const int b  = blockIdx.z;

    // Load Q tile 256x64, transposed to k-major.
    #pragma unroll
    for (int r = 0; r < 16; r++) {
        int idx = tid + r * 256;
        int row = idx >> 4;              // 0..255
        int c4  = (idx & 15) * 4;
        float4 q = *(const float4*)&g_Q[((size_t)(b * Tv + t0 + row)) * HIDv + h * DKv + c4];
        Qs[(c4 + 0) * 260 + row] = q.x;
        Qs[(c4 + 1) * 260 + row] = q.y;
        Qs[(c4 + 2) * 260 + row] = q.z;
        Qs[(c4 + 3) * 260 + row] = q.w;
    }

    float rowM[8], rowL[8];
    #pragma unroll
    for (int i = 0; i < 8; i++) { rowM[i] = -1e30f; rowL[i] = 0.0f; }

    u64 acc2[8][4];
    #pragma unroll
    for (int i = 0; i < 8; i++)
        #pragma unroll
        for (int j = 0; j < 4; j++) acc2[i][j] = 0ull;

    const int Xst = (tx & 3) << 2;       // store-side swizzle constant
    __syncthreads();

    for (int s0 = 0; s0 < Sv; s0 += 64) {
        // Load K (transposed to k-major), V (natural), mask strip.
        #pragma unroll
        for (int r = 0; r < 4; r++) {
            int idx = tid + r * 256;
            int row = idx >> 4;          // 0..63
            int c4  = (idx & 15) * 4;
            size_t g = ((size_t)(b * Sv + s0 + row)) * HIDv + h * DKv + c4;
            float4 k = *(const float4*)&g_K[g];
            Ks[(c4 + 0) * 68 + row] = k.x;
            Ks[(c4 + 1) * 68 + row] = k.y;
            Ks[(c4 + 2) * 68 + row] = k.z;
            Ks[(c4 + 3) * 68 + row] = k.w;
            float4 v = *(const float4*)&g_V[g];
            *(float4*)&Vs[row * 68 + c4] = v;
        }
        if (tid < 64) mneg[tid] = (mask[b * Sv + s0 + tid] != 0) ? 0.0f : -1e20f;
        __syncthreads();

        // QK^T: sc2[i][j] packed over key-pairs.
        u64 sc2[8][4];
        #pragma unroll
        for (int i = 0; i < 8; i++)
            #pragma unroll
            for (int j = 0; j < 4; j++) sc2[i][j] = 0ull;

        #pragma unroll 8
        for (int kk = 0; kk < 64; kk++) {
            float4 a0 = *(const float4*)&Qs[kk * 260 + ty * 8];
            float4 a1 = *(const float4*)&Qs[kk * 260 + ty * 8 + 4];
            ulonglong2 b0 = *(const ulonglong2*)&Ks[kk * 68 + tx * 8];
            ulonglong2 b1 = *(const ulonglong2*)&Ks[kk * 68 + tx * 8 + 4];
            u64 bb2[4] = {b0.x, b0.y, b1.x, b1.y};
            u64 a2[8];
            a2[0] = pdup(a0.x); a2[1] = pdup(a0.y);
            a2[2] = pdup(a0.z); a2[3] = pdup(a0.w);
            a2[4] = pdup(a1.x); a2[5] = pdup(a1.y);
            a2[6] = pdup(a1.z); a2[7] = pdup(a1.w);
            #pragma unroll
            for (int i = 0; i < 8; i++)
                #pragma unroll
                for (int j = 0; j < 4; j++)
                    sc2[i][j] = fma2(a2[i], bb2[j], sc2[i][j]);
        }

        // scale + mask (packed)
        {
            ulonglong2 m0 = *(const ulonglong2*)&mneg[tx * 8];
            ulonglong2 m1 = *(const ulonglong2*)&mneg[tx * 8 + 4];
            u64 mm[4] = {m0.x, m0.y, m1.x, m1.y};
            u64 c18 = pdup(0.125f);
            #pragma unroll
            for (int i = 0; i < 8; i++)
                #pragma unroll
                for (int j = 0; j < 4; j++)
                    sc2[i][j] = fma2(sc2[i][j], c18, mm[j]);
        }

        // Online softmax per row (8 lanes per row; shfl width 8), store P transposed.
        #pragma unroll
        for (int i = 0; i < 8; i++) {
            float s8[8];
            unpack2(sc2[i][0], s8[0], s8[1]);
            unpack2(sc2[i][1], s8[2], s8[3]);
            unpack2(sc2[i][2], s8[4], s8[5]);
            unpack2(sc2[i][3], s8[6], s8[7]);
            float mx = fmaxf(fmaxf(fmaxf(s8[0], s8[1]), fmaxf(s8[2], s8[3])),
                             fmaxf(fmaxf(s8[4], s8[5]), fmaxf(s8[6], s8[7])));
            #pragma unroll
            for (int o = 4; o >= 1; o >>= 1)
                mx = fmaxf(mx, __shfl_xor_sync(0xffffffffu, mx, o, 8));

            float mnw = fmaxf(rowM[i], mx);
            float f   = fast_exp(rowM[i] - mnw);
            rowM[i] = mnw;

            float p[8], se = 0.0f;
            #pragma unroll
            for (int k = 0; k < 8; k++) { p[k] = fast_exp(s8[k] - mnw); se += p[k]; }
            #pragma unroll
            for (int o = 4; o >= 1; o >>= 1)
                se += __shfl_xor_sync(0xffffffffu, se, o, 8);
            rowL[i] = rowL[i] * f + se;

            u64 f2 = pdup(f);
            #pragma unroll
            for (int j = 0; j < 4; j++) acc2[i][j] = mul2(acc2[i][j], f2);

            int colp = (ty * 8 + i) ^ Xst;
            #pragma unroll
            for (int j = 0; j < 8; j++)
                Ps[(tx * 8 + j) * 260 + colp] = p[j];
        }
        __syncthreads();

        // acc += P @ V   (p loads de-swizzled, vectorized)
        #pragma unroll 2
        for (int g = 0; g < 8; g++) {
            const int X    = (g & 3) << 2;
            const int base = (ty * 8) ^ (X & 8);
            const int offA = base + (X & 4);          // logical i 0..3
            const int offB = base + ((X & 4) ^ 4);    // logical i 4..7
            #pragma unroll
            for (int js = 0; js < 8; js++) {
                int s = g * 8 + js;
                ulonglong2 pa = *(const ulonglong2*)&Ps[s * 260 + offA];
                ulonglong2 pb = *(const ulonglong2*)&Ps[s * 260 + offB];
                float p0, p1, p2v, p3, p4, p5, p6, p7;
                unpack2(pa.x, p0, p1); unpack2(pa.y, p2v, p3);
                unpack2(pb.x, p4, p5); unpack2(pb.y, p6, p7);
                u64 pp[8] = {pdup(p0), pdup(p1), pdup(p2v), pdup(p3),
                             pdup(p4), pdup(p5), pdup(p6),  pdup(p7)};
                ulonglong2 v0 = *(const ulonglong2*)&Vs[s * 68 + tx * 8];
                ulonglong2 v1 = *(const ulonglong2*)&Vs[s * 68 + tx * 8 + 4];
                u64 vv[4] = {v0.x, v0.y, v1.x, v1.y};
                #pragma unroll
                for (int i = 0; i < 8; i++)
                    #pragma unroll
                    for (int j = 0; j < 4; j++)
                        acc2[i][j] = fma2(pp[i], vv[j], acc2[i][j]);
            }
        }
        __syncthreads();
    }

    // normalize + write ctx
    #pragma unroll
    for (int i = 0; i < 8; i++) {
        float inv = 1.0f / rowL[i];
        float o[8];
        unpack2(acc2[i][0], o[0], o[1]);
        unpack2(acc2[i][1], o[2], o[3]);
        unpack2(acc2[i][2], o[4], o[5]);
        unpack2(acc2[i][3], o[6], o[7]);
        float4 s0, s1;
        s0.x = o[0] * inv; s0.y = o[1] * inv; s0.z = o[2] * inv; s0.w = o[3] * inv;
        s1.x = o[4] * inv; s1.y = o[5] * inv; s1.z = o[6] * inv; s1.w = o[7] * inv;
        size_t base = ((size_t)(b * Tv + t0 + ty * 8 + i)) * HIDv + h * DKv + tx * 8;
        *(float4*)&g_ctx[base]     = s0;
        *(float4*)&g_ctx[base + 4] = s1;
    }
}

// ---------------------------------------------------------------------------

extern "C" void kernel_launch(void* const* d_in, const int* in_sizes, int n_in,
                              void* d_out, int out_size)
{
    const float* inputs  = (const float*)d_in[0];
    const float* targets = (const float*)d_in[1];
    const int*   mask    = (const int*)d_in[2];     // bool widened to int32
    const float* Wq = (const float*)d_in[3];
    const float* bq = (const float*)d_in[4];
    const float* Wk = (const float*)d_in[5];
    const float* bk = (const float*)d_in[6];
    const float* Wv = (const float*)d_in[7];
    const float* bv = (const float*)d_in[8];
    const float* Wo = (const float*)d_in[9];
    const float* bo = (const float*)d_in[10];
    float* out = (float*)d_out;

    float *pQ, *pK, *pV, *pC;
    cudaGetSymbolAddress((void**)&pQ, g_Q);
    cudaGetSymbolAddress((void**)&pK, g_K);
    cudaGetSymbolAddress((void**)&pV, g_V);
    cudaGetSymbolAddress((void**)&pC, g_ctx);

    const int ATTN_SMEM = (64 * 260 + 64 * 68 + 64 * 68 + 64 * 260 + 64) * (int)sizeof(float);
    cudaFuncSetAttribute(attn_kernel, cudaFuncAttributeMaxDynamicSharedMemorySize, ATTN_SMEM);

    dim3 blk256(256);

    // Q = targets @ Wq^T + bq    (M = B*T = 4096)
    gemm_bias_kernel<<<dim3(4, 32), blk256>>>(targets, Wq, bq, pQ, Bv * Tv);
    // K = inputs @ Wk^T + bk     (M = B*S = 32768)
    gemm_bias_kernel<<<dim3(4, 256), blk256>>>(inputs, Wk, bk, pK, Bv * Sv);
    // V = inputs @ Wv^T + bv
    gemm_bias_kernel<<<dim3(4, 256), blk256>>>(inputs, Wv, bv, pV, Bv * Sv);
    // attention -> g_ctx   (256-query tiles: 2 per (b,h) -> 128 blocks)
    attn_kernel<<<dim3(Tv / 256, HEADSv, Bv), blk256, ATTN_SMEM>>>(mask);
    // out = ctx @ Wo^T + bo
    gemm_bias_kernel<<<dim3(4, 32), blk256>>>(pC, Wo, bo, out, Bv * Tv);
}